// round 1
// baseline (speedup 1.0000x reference)
#include <cuda_runtime.h>
#include <math.h>

#define N0c 409600
#define N1c 102400
#define N2c 25600
#define N3c 4096
#define E0c 1536000
#define E1c 256000
#define E2c 40960
#define DIN 100
#define DH  256
#define DOUTc 47

// ---------------- scratch (device globals; no allocation allowed) ------------
__device__ float g_sum0[(size_t)N1c * DIN];
__device__ float g_cnt0[N1c];
__device__ float g_h1[(size_t)N1c * DH];
__device__ float g_sum1[(size_t)N2c * DH];
__device__ float g_cnt1[N2c];
__device__ float g_sum2[(size_t)N3c * DH];
__device__ float g_cnt2[N3c];
__device__ float g_W0[(2 * DIN) * DH];   // [K=200][N=256]
__device__ float g_W1[(2 * DH) * DH];    // [K=512][N=256]
__device__ float g_W2[(2 * DH) * DOUTc]; // [K=512][N=47]

// ---------------- zero all accumulators --------------------------------------
__global__ void zero_all() {
    size_t i = (size_t)blockIdx.x * blockDim.x + threadIdx.x;
    size_t stride = (size_t)gridDim.x * blockDim.x;
    const size_t n0 = (size_t)N1c * DIN / 4;
    const size_t n1 = (size_t)N2c * DH / 4;
    const size_t n2 = (size_t)N3c * DH / 4;
    float4 z = make_float4(0.f, 0.f, 0.f, 0.f);
    float4* s0 = (float4*)g_sum0;
    float4* s1 = (float4*)g_sum1;
    float4* s2 = (float4*)g_sum2;
    for (size_t t = i; t < n0; t += stride) s0[t] = z;
    for (size_t t = i; t < n1; t += stride) s1[t] = z;
    for (size_t t = i; t < n2; t += stride) s2[t] = z;
    for (size_t t = i; t < N1c; t += stride) g_cnt0[t] = 0.f;
    for (size_t t = i; t < N2c; t += stride) g_cnt1[t] = 0.f;
    for (size_t t = i; t < N3c; t += stride) g_cnt2[t] = 0.f;
}

// ---------------- weight transpose/concat: Wc[k][n] --------------------------
__global__ void wtrans(const float* __restrict__ Wl, const float* __restrict__ Wr,
                       float* __restrict__ Wc, int d, int n, int K) {
    int total = K * n;
    for (int idx = blockIdx.x * blockDim.x + threadIdx.x; idx < total;
         idx += gridDim.x * blockDim.x) {
        int k = idx / n;
        int col = idx % n;
        float v = (k < d) ? Wl[col * d + k] : Wr[col * d + (k - d)];
        Wc[idx] = v;
    }
}

// ---------------- edge scatter, d=100 ----------------------------------------
__global__ void scatter100(const float* __restrict__ x, const int* __restrict__ src,
                           const int* __restrict__ dst, int E) {
    int warp = (blockIdx.x * blockDim.x + threadIdx.x) >> 5;
    int lane = threadIdx.x & 31;
    if (warp >= E) return;
    int s = src[warp];
    int d = dst[warp];
    const float* xs = x + (size_t)s * DIN;
    float* o = g_sum0 + (size_t)d * DIN;
    #pragma unroll
    for (int k = lane; k < DIN; k += 32) atomicAdd(o + k, xs[k]);
    if (lane == 0) atomicAdd(&g_cnt0[d], 1.f);
}

// ---------------- edge scatter, d=256 ----------------------------------------
__global__ void scatter256(const float* __restrict__ xin, const int* __restrict__ src,
                           const int* __restrict__ dst, int E,
                           float* __restrict__ sum, float* __restrict__ cnt) {
    int warp = (blockIdx.x * blockDim.x + threadIdx.x) >> 5;
    int lane = threadIdx.x & 31;
    if (warp >= E) return;
    int s = src[warp];
    int d = dst[warp];
    const float4* xs = (const float4*)(xin + (size_t)s * DH);
    float* o = sum + (size_t)d * DH;
    #pragma unroll
    for (int i = lane; i < DH / 4; i += 32) {
        float4 v = xs[i];
        int k = i * 4;
        atomicAdd(o + k + 0, v.x);
        atomicAdd(o + k + 1, v.y);
        atomicAdd(o + k + 2, v.z);
        atomicAdd(o + k + 3, v.w);
    }
    if (lane == 0) atomicAdd(cnt + d, 1.f);
}

// ---------------- in-place mean: sum[r][*] *= 1/max(cnt[r],1) ----------------
__global__ void mean_scale(float* __restrict__ sum, const float* __restrict__ cnt, int d) {
    int r = blockIdx.x;
    float inv = 1.f / fmaxf(cnt[r], 1.f);
    float* p = sum + (size_t)r * d;
    for (int k = threadIdx.x; k < d; k += blockDim.x) p[k] *= inv;
}

// ---------------- SGEMM: C = [A1|A2] @ B + bias (optional relu) --------------
// A1: [M,K1] row-major, A2: [M,K2] row-major, B: [K1+K2, N] row-major
#define BM 128
#define BN 128
#define BKc 8
#define TM 8
#define TN 8
__global__ void __launch_bounds__(256)
gemm_dual(const float* __restrict__ A1, int K1, const float* __restrict__ A2, int K2,
          const float* __restrict__ B, const float* __restrict__ bias,
          float* __restrict__ C, int M, int Nn, int relu) {
    __shared__ float As[BKc][BM];
    __shared__ float Bs[BKc][BN];
    int tid = threadIdx.x;
    int row0 = blockIdx.y * BM;
    int col0 = blockIdx.x * BN;
    int K = K1 + K2;
    int tx = tid % 16, ty = tid / 16;
    float acc[TM][TN] = {};
    int aM = tid >> 1;
    int aK = (tid & 1) * 4;
    int bK = tid >> 5;
    int bN = (tid & 31) * 4;

    for (int k0 = 0; k0 < K; k0 += BKc) {
        #pragma unroll
        for (int i = 0; i < 4; i++) {
            int gk = k0 + aK + i;
            int gr = row0 + aM;
            float v;
            if (gk < K1) v = A1[(size_t)gr * K1 + gk];
            else         v = A2[(size_t)gr * K2 + (gk - K1)];
            As[aK + i][aM] = v;
        }
        float4 bv = *(const float4*)&B[(size_t)(k0 + bK) * Nn + col0 + bN];
        *(float4*)&Bs[bK][bN] = bv;
        __syncthreads();
        #pragma unroll
        for (int kk = 0; kk < BKc; kk++) {
            float af[TM], bf[TN];
            #pragma unroll
            for (int i = 0; i < TM; i++) af[i] = As[kk][ty * TM + i];
            #pragma unroll
            for (int j = 0; j < TN; j++) bf[j] = Bs[kk][tx * TN + j];
            #pragma unroll
            for (int i = 0; i < TM; i++)
                #pragma unroll
                for (int j = 0; j < TN; j++) acc[i][j] += af[i] * bf[j];
        }
        __syncthreads();
    }
    #pragma unroll
    for (int i = 0; i < TM; i++) {
        int r = row0 + ty * TM + i;
        #pragma unroll
        for (int j = 0; j < TN; j++) {
            int c = col0 + tx * TN + j;
            float v = acc[i][j] + bias[c];
            if (relu) v = fmaxf(v, 0.f);
            C[(size_t)r * Nn + c] = v;
        }
    }
}

// ---------------- layer 2 (N=47) + log_softmax, fused ------------------------
__global__ void layer2_softmax(const float* __restrict__ h2, const float* __restrict__ bias,
                               float* __restrict__ h3out, float* __restrict__ lsmout) {
    int r = blockIdx.x;
    __shared__ float a[2 * DH];
    __shared__ float vals[DOUTc];
    __shared__ float Lse;
    float inv = 1.f / fmaxf(g_cnt2[r], 1.f);
    for (int k = threadIdx.x; k < DH; k += blockDim.x)
        a[k] = g_sum2[(size_t)r * DH + k] * inv;
    for (int k = threadIdx.x; k < DH; k += blockDim.x)
        a[DH + k] = h2[(size_t)r * DH + k];
    __syncthreads();
    int j = threadIdx.x;
    float v = 0.f;
    if (j < DOUTc) {
        v = bias[j];
        #pragma unroll 8
        for (int k = 0; k < 2 * DH; k++) v += a[k] * g_W2[k * DOUTc + j];
        vals[j] = v;
        h3out[(size_t)r * DOUTc + j] = v;
    }
    __syncthreads();
    if (threadIdx.x == 0) {
        float m = -1e30f;
        for (int t = 0; t < DOUTc; t++) m = fmaxf(m, vals[t]);
        float s = 0.f;
        for (int t = 0; t < DOUTc; t++) s += expf(vals[t] - m);
        Lse = m + logf(s);
    }
    __syncthreads();
    if (j < DOUTc) lsmout[(size_t)r * DOUTc + j] = v - Lse;
}

// ---------------- launch -----------------------------------------------------
extern "C" void kernel_launch(void* const* d_in, const int* in_sizes, int n_in,
                              void* d_out, int out_size) {
    const float* x   = (const float*)d_in[0];
    const float* Wl0 = (const float*)d_in[1];
    const float* bl0 = (const float*)d_in[2];
    const float* Wr0 = (const float*)d_in[3];
    const float* Wl1 = (const float*)d_in[4];
    const float* bl1 = (const float*)d_in[5];
    const float* Wr1 = (const float*)d_in[6];
    const float* Wl2 = (const float*)d_in[7];
    const float* bl2 = (const float*)d_in[8];
    const float* Wr2 = (const float*)d_in[9];
    const int* src0 = (const int*)d_in[10];
    const int* dst0 = (const int*)d_in[11];
    const int* src1 = (const int*)d_in[12];
    const int* dst1 = (const int*)d_in[13];
    const int* src2 = (const int*)d_in[14];
    const int* dst2 = (const int*)d_in[15];

    int e0 = in_sizes[10], e1 = in_sizes[12], e2 = in_sizes[14];

    float* out = (float*)d_out;
    float* lsm = out;                       // 4096*47
    float* h3  = out + (size_t)N3c * DOUTc; // 4096*47
    float* h2  = h3 + (size_t)N3c * DOUTc;  // 25600*256

    // resolve device-global pointers (query API; capture-safe, no allocation)
    float *p_sum0, *p_cnt0, *p_h1, *p_sum1, *p_cnt1, *p_W0, *p_W1, *p_W2;
    cudaGetSymbolAddress((void**)&p_sum0, g_sum0);
    cudaGetSymbolAddress((void**)&p_cnt0, g_cnt0);
    cudaGetSymbolAddress((void**)&p_h1,   g_h1);
    cudaGetSymbolAddress((void**)&p_sum1, g_sum1);
    cudaGetSymbolAddress((void**)&p_cnt1, g_cnt1);
    cudaGetSymbolAddress((void**)&p_W0,   g_W0);
    cudaGetSymbolAddress((void**)&p_W1,   g_W1);
    cudaGetSymbolAddress((void**)&p_W2,   g_W2);
    float *p_sum2, *p_cnt2;
    cudaGetSymbolAddress((void**)&p_sum2, g_sum2);
    cudaGetSymbolAddress((void**)&p_cnt2, g_cnt2);

    zero_all<<<2048, 256>>>();
    wtrans<<<200, 256>>>(Wl0, Wr0, p_W0, DIN, DH, 2 * DIN);
    wtrans<<<512, 256>>>(Wl1, Wr1, p_W1, DH, DH, 2 * DH);
    wtrans<<<96, 256>>>(Wl2, Wr2, p_W2, DH, DOUTc, 2 * DH);

    // ---- layer 0 ----
    scatter100<<<(e0 + 7) / 8, 256>>>(x, src0, dst0, e0);
    mean_scale<<<N1c, 128>>>(p_sum0, p_cnt0, DIN);
    {
        dim3 grid(DH / BN, N1c / BM);
        gemm_dual<<<grid, 256>>>(p_sum0, DIN, x, DIN, p_W0, bl0, p_h1, N1c, DH, 1);
    }

    // ---- layer 1 ----
    scatter256<<<(e1 + 7) / 8, 256>>>(p_h1, src1, dst1, e1, p_sum1, p_cnt1);
    mean_scale<<<N2c, 256>>>(p_sum1, p_cnt1, DH);
    {
        dim3 grid(DH / BN, N2c / BM);
        gemm_dual<<<grid, 256>>>(p_sum1, DH, p_h1, DH, p_W1, bl1, h2, N2c, DH, 1);
    }

    // ---- layer 2 ----
    scatter256<<<(e2 + 7) / 8, 256>>>(h2, src2, dst2, e2, p_sum2, p_cnt2);
    layer2_softmax<<<N3c, 64>>>(h2, bl2, h3, lsm);
}

// round 2
// speedup vs baseline: 1.4842x; 1.4842x over previous
#include <cuda_runtime.h>
#include <math.h>

#define N0c 409600
#define N1c 102400
#define N2c 25600
#define N3c 4096
#define E0c 1536000
#define E1c 256000
#define E2c 40960
#define DIN 100
#define DH  256
#define DOUTc 47

// ---------------- scratch (device globals; no allocation allowed) ------------
__device__ float g_mean0[(size_t)N1c * DIN];
__device__ float g_h1[(size_t)N1c * DH];
__device__ float g_mean1[(size_t)N2c * DH];
__device__ float g_mean2[(size_t)N3c * DH];
__device__ float g_W0[(2 * DIN) * DH];   // [K=200][N=256]
__device__ float g_W1[(2 * DH) * DH];    // [K=512][N=256]
__device__ float g_W2[(2 * DH) * DOUTc]; // [K=512][N=47]

// CSR scratch
__device__ int g_cnt0[N1c];
__device__ int g_off0[N1c + 1];
__device__ int g_cur0[N1c];
__device__ int g_csr0[E0c];
__device__ int g_cnt1[N2c];
__device__ int g_off1[N2c + 1];
__device__ int g_cur1[N2c];
__device__ int g_csr1[E1c];
__device__ int g_cnt2[N3c];
__device__ int g_off2[N3c + 1];
__device__ int g_cur2[N3c];
__device__ int g_csr2[E2c];
__device__ int g_incl[N1c];
__device__ int g_bsum[256];

// ---------------- zero int counters ------------------------------------------
__global__ void zero_cnts() {
    int i = blockIdx.x * blockDim.x + threadIdx.x;
    int stride = gridDim.x * blockDim.x;
    for (int t = i; t < N1c; t += stride) g_cnt0[t] = 0;
    for (int t = i; t < N2c; t += stride) g_cnt1[t] = 0;
    for (int t = i; t < N3c; t += stride) g_cnt2[t] = 0;
}

// ---------------- weight transpose/concat: Wc[k][n] --------------------------
__global__ void wtrans(const float* __restrict__ Wl, const float* __restrict__ Wr,
                       float* __restrict__ Wc, int d, int n, int K) {
    int total = K * n;
    for (int idx = blockIdx.x * blockDim.x + threadIdx.x; idx < total;
         idx += gridDim.x * blockDim.x) {
        int k = idx / n;
        int col = idx % n;
        float v = (k < d) ? Wl[col * d + k] : Wr[col * d + (k - d)];
        Wc[idx] = v;
    }
}

// ---------------- CSR build ---------------------------------------------------
__global__ void hist_k(const int* __restrict__ dst, int E, int* __restrict__ cnt) {
    for (int e = blockIdx.x * blockDim.x + threadIdx.x; e < E;
         e += gridDim.x * blockDim.x)
        atomicAdd(&cnt[dst[e]], 1);
}

__global__ void scan_blk(const int* __restrict__ cnt, int n, int* __restrict__ incl) {
    __shared__ int sh[1024];
    int i = blockIdx.x * 1024 + threadIdx.x;
    int v = (i < n) ? cnt[i] : 0;
    sh[threadIdx.x] = v;
    __syncthreads();
    for (int d = 1; d < 1024; d <<= 1) {
        int t = (threadIdx.x >= d) ? sh[threadIdx.x - d] : 0;
        __syncthreads();
        sh[threadIdx.x] += t;
        __syncthreads();
    }
    if (i < n) incl[i] = sh[threadIdx.x];
    if (threadIdx.x == 1023) g_bsum[blockIdx.x] = sh[1023];
}

__global__ void scan_top(int nb) {
    __shared__ int sh[256];
    int t = threadIdx.x;
    int v = (t < nb) ? g_bsum[t] : 0;
    sh[t] = v;
    __syncthreads();
    for (int d = 1; d < 256; d <<= 1) {
        int u = (t >= d) ? sh[t - d] : 0;
        __syncthreads();
        sh[t] += u;
        __syncthreads();
    }
    if (t < nb) g_bsum[t] = sh[t] - v;  // exclusive block offsets
}

__global__ void scan_fin(const int* __restrict__ cnt, const int* __restrict__ incl,
                         int n, int* __restrict__ off, int* __restrict__ cur) {
    int i = blockIdx.x * 1024 + threadIdx.x;
    if (i < n) {
        int o = incl[i] - cnt[i] + g_bsum[blockIdx.x];
        off[i] = o;
        cur[i] = o;
        if (i == n - 1) off[n] = incl[i] + g_bsum[blockIdx.x];
    }
}

__global__ void fill_k(const int* __restrict__ src, const int* __restrict__ dst, int E,
                       int* __restrict__ cur, int* __restrict__ csr) {
    for (int e = blockIdx.x * blockDim.x + threadIdx.x; e < E;
         e += gridDim.x * blockDim.x) {
        int p = atomicAdd(&cur[dst[e]], 1);
        csr[p] = src[e];
    }
}

// ---------------- gather-mean, d=100 (25 float4/row) --------------------------
__global__ void gather_mean100(const float* __restrict__ x, const int* __restrict__ off,
                               const int* __restrict__ csr, float* __restrict__ mean,
                               int n) {
    int w = (blockIdx.x * blockDim.x + threadIdx.x) >> 5;
    int lane = threadIdx.x & 31;
    if (w >= n) return;
    int e0 = off[w], e1 = off[w + 1];
    float4 acc = make_float4(0.f, 0.f, 0.f, 0.f);
    for (int e = e0; e < e1; e++) {
        int s = csr[e];
        if (lane < 25) {
            float4 v = *((const float4*)(x + (size_t)s * DIN) + lane);
            acc.x += v.x; acc.y += v.y; acc.z += v.z; acc.w += v.w;
        }
    }
    float inv = 1.f / fmaxf((float)(e1 - e0), 1.f);
    if (lane < 25) {
        acc.x *= inv; acc.y *= inv; acc.z *= inv; acc.w *= inv;
        *((float4*)(mean + (size_t)w * DIN) + lane) = acc;
    }
}

// ---------------- gather-mean, d=256 (64 float4/row) ---------------------------
__global__ void gather_mean256(const float* __restrict__ xin, const int* __restrict__ off,
                               const int* __restrict__ csr, float* __restrict__ mean,
                               int n) {
    int w = (blockIdx.x * blockDim.x + threadIdx.x) >> 5;
    int lane = threadIdx.x & 31;
    if (w >= n) return;
    int e0 = off[w], e1 = off[w + 1];
    float4 a0 = make_float4(0.f, 0.f, 0.f, 0.f);
    float4 a1 = a0;
    for (int e = e0; e < e1; e++) {
        int s = csr[e];
        const float4* xs = (const float4*)(xin + (size_t)s * DH);
        float4 v0 = xs[lane];
        float4 v1 = xs[lane + 32];
        a0.x += v0.x; a0.y += v0.y; a0.z += v0.z; a0.w += v0.w;
        a1.x += v1.x; a1.y += v1.y; a1.z += v1.z; a1.w += v1.w;
    }
    float inv = 1.f / fmaxf((float)(e1 - e0), 1.f);
    a0.x *= inv; a0.y *= inv; a0.z *= inv; a0.w *= inv;
    a1.x *= inv; a1.y *= inv; a1.z *= inv; a1.w *= inv;
    float4* mp = (float4*)(mean + (size_t)w * DH);
    mp[lane] = a0;
    mp[lane + 32] = a1;
}

// ---------------- SGEMM: C = [A1|A2] @ B + bias (optional relu) ---------------
// Packed fp32x2 FFMA2 path, BK=16, double-buffered smem.
#define BM 128
#define BN 128
#define BKc 16
__global__ void __launch_bounds__(256)
gemm_dual(const float* __restrict__ A1, int K1, const float* __restrict__ A2, int K2,
          const float* __restrict__ B, const float* __restrict__ bias,
          float* __restrict__ C, int M, int Nn, int relu) {
    __shared__ float As[2][BKc][BM];
    __shared__ float Bs[2][BKc][BN];
    int tid = threadIdx.x;
    int row0 = blockIdx.y * BM;
    int col0 = blockIdx.x * BN;
    int K = K1 + K2;
    int m = tid >> 1, kb = (tid & 1) * 8;          // A-load mapping
    int kb2 = tid >> 4, nb = (tid & 15) * 8;       // B-load mapping
    int tx = tid & 15, ty = tid >> 4;              // compute mapping
    const float* Arow1 = A1 + (size_t)(row0 + m) * K1;
    const float* Arow2 = A2 + (size_t)(row0 + m) * K2;

    unsigned long long acc[8][4];
    #pragma unroll
    for (int i = 0; i < 8; i++)
        #pragma unroll
        for (int j = 0; j < 4; j++) acc[i][j] = 0ull;

    // prologue: tile 0
    {
        #pragma unroll
        for (int i = 0; i < 8; i++) {
            int gk = kb + i;
            float v = 0.f;
            if (gk < K1) v = Arow1[gk];
            else if (gk < K) v = Arow2[gk - K1];
            As[0][kb + i][m] = v;
        }
        float4 b0 = make_float4(0.f, 0.f, 0.f, 0.f), b1 = b0;
        if (kb2 < K) {
            const float* bp = B + (size_t)kb2 * Nn + col0 + nb;
            b0 = *(const float4*)bp;
            b1 = *(const float4*)(bp + 4);
        }
        *(float4*)&Bs[0][kb2][nb] = b0;
        *(float4*)&Bs[0][kb2][nb + 4] = b1;
    }
    __syncthreads();

    int T = (K + BKc - 1) / BKc;
    for (int t = 0; t < T; t++) {
        int curb = t & 1;
        float ar[8];
        float4 br0, br1;
        bool has = (t + 1 < T);
        if (has) {
            int k0 = (t + 1) * BKc;
            #pragma unroll
            for (int i = 0; i < 8; i++) {
                int gk = k0 + kb + i;
                float v = 0.f;
                if (gk < K1) v = Arow1[gk];
                else if (gk < K) v = Arow2[gk - K1];
                ar[i] = v;
            }
            int gk = k0 + kb2;
            br0 = make_float4(0.f, 0.f, 0.f, 0.f);
            br1 = br0;
            if (gk < K) {
                const float* bp = B + (size_t)gk * Nn + col0 + nb;
                br0 = *(const float4*)bp;
                br1 = *(const float4*)(bp + 4);
            }
        }
        #pragma unroll
        for (int kk = 0; kk < BKc; kk++) {
            float4 a0 = *(const float4*)&As[curb][kk][ty * 8];
            float4 a1 = *(const float4*)&As[curb][kk][ty * 8 + 4];
            ulonglong2 q0 = *(const ulonglong2*)&Bs[curb][kk][tx * 8];
            ulonglong2 q1 = *(const ulonglong2*)&Bs[curb][kk][tx * 8 + 4];
            unsigned long long b2[4] = {q0.x, q0.y, q1.x, q1.y};
            float af[8] = {a0.x, a0.y, a0.z, a0.w, a1.x, a1.y, a1.z, a1.w};
            #pragma unroll
            for (int i = 0; i < 8; i++) {
                unsigned long long ad;
                asm("mov.b64 %0, {%1, %1};" : "=l"(ad) : "f"(af[i]));
                #pragma unroll
                for (int j = 0; j < 4; j++)
                    asm("fma.rn.f32x2 %0, %1, %2, %0;"
                        : "+l"(acc[i][j]) : "l"(ad), "l"(b2[j]));
            }
        }
        if (has) {
            int nxt = curb ^ 1;
            #pragma unroll
            for (int i = 0; i < 8; i++) As[nxt][kb + i][m] = ar[i];
            *(float4*)&Bs[nxt][kb2][nb] = br0;
            *(float4*)&Bs[nxt][kb2][nb + 4] = br1;
        }
        __syncthreads();
    }

    float bv[8];
    #pragma unroll
    for (int j = 0; j < 8; j++) bv[j] = bias[col0 + tx * 8 + j];
    #pragma unroll
    for (int i = 0; i < 8; i++) {
        float o[8];
        #pragma unroll
        for (int j = 0; j < 4; j++) {
            float lo, hi;
            asm("mov.b64 {%0, %1}, %2;" : "=f"(lo), "=f"(hi) : "l"(acc[i][j]));
            o[2 * j] = lo;
            o[2 * j + 1] = hi;
        }
        #pragma unroll
        for (int j = 0; j < 8; j++) {
            o[j] += bv[j];
            if (relu) o[j] = fmaxf(o[j], 0.f);
        }
        float4* cp = (float4*)&C[(size_t)(row0 + ty * 8 + i) * Nn + col0 + tx * 8];
        cp[0] = make_float4(o[0], o[1], o[2], o[3]);
        cp[1] = make_float4(o[4], o[5], o[6], o[7]);
    }
}

// ---------------- layer 2 (N=47) + log_softmax, fused -------------------------
__global__ void layer2_softmax(const float* __restrict__ h2, const float* __restrict__ bias,
                               float* __restrict__ h3out, float* __restrict__ lsmout) {
    int r = blockIdx.x;
    __shared__ float a[2 * DH];
    __shared__ float vals[DOUTc];
    __shared__ float Lse;
    for (int k = threadIdx.x; k < DH; k += blockDim.x)
        a[k] = g_mean2[(size_t)r * DH + k];
    for (int k = threadIdx.x; k < DH; k += blockDim.x)
        a[DH + k] = h2[(size_t)r * DH + k];
    __syncthreads();
    int j = threadIdx.x;
    float v = 0.f;
    if (j < DOUTc) {
        v = bias[j];
        #pragma unroll 8
        for (int k = 0; k < 2 * DH; k++) v += a[k] * g_W2[k * DOUTc + j];
        vals[j] = v;
        h3out[(size_t)r * DOUTc + j] = v;
    }
    __syncthreads();
    if (threadIdx.x == 0) {
        float mmax = -1e30f;
        for (int t = 0; t < DOUTc; t++) mmax = fmaxf(mmax, vals[t]);
        float s = 0.f;
        for (int t = 0; t < DOUTc; t++) s += expf(vals[t] - mmax);
        Lse = mmax + logf(s);
    }
    __syncthreads();
    if (j < DOUTc) lsmout[(size_t)r * DOUTc + j] = v - Lse;
}

// ---------------- launch -----------------------------------------------------
extern "C" void kernel_launch(void* const* d_in, const int* in_sizes, int n_in,
                              void* d_out, int out_size) {
    const float* x   = (const float*)d_in[0];
    const float* Wl0 = (const float*)d_in[1];
    const float* bl0 = (const float*)d_in[2];
    const float* Wr0 = (const float*)d_in[3];
    const float* Wl1 = (const float*)d_in[4];
    const float* bl1 = (const float*)d_in[5];
    const float* Wr1 = (const float*)d_in[6];
    const float* Wl2 = (const float*)d_in[7];
    const float* bl2 = (const float*)d_in[8];
    const float* Wr2 = (const float*)d_in[9];
    const int* src0 = (const int*)d_in[10];
    const int* dst0 = (const int*)d_in[11];
    const int* src1 = (const int*)d_in[12];
    const int* dst1 = (const int*)d_in[13];
    const int* src2 = (const int*)d_in[14];
    const int* dst2 = (const int*)d_in[15];

    int e0 = in_sizes[10], e1 = in_sizes[12], e2 = in_sizes[14];

    float* out = (float*)d_out;
    float* lsm = out;                       // 4096*47
    float* h3  = out + (size_t)N3c * DOUTc; // 4096*47
    float* h2  = h3 + (size_t)N3c * DOUTc;  // 25600*256

    float *p_mean0, *p_h1, *p_mean1, *p_mean2, *p_W0, *p_W1, *p_W2;
    cudaGetSymbolAddress((void**)&p_mean0, g_mean0);
    cudaGetSymbolAddress((void**)&p_h1,    g_h1);
    cudaGetSymbolAddress((void**)&p_mean1, g_mean1);
    cudaGetSymbolAddress((void**)&p_mean2, g_mean2);
    cudaGetSymbolAddress((void**)&p_W0,    g_W0);
    cudaGetSymbolAddress((void**)&p_W1,    g_W1);
    cudaGetSymbolAddress((void**)&p_W2,    g_W2);
    int *p_cnt0, *p_off0, *p_cur0, *p_csr0;
    int *p_cnt1, *p_off1, *p_cur1, *p_csr1;
    int *p_cnt2, *p_off2, *p_cur2, *p_csr2;
    int *p_incl;
    cudaGetSymbolAddress((void**)&p_cnt0, g_cnt0);
    cudaGetSymbolAddress((void**)&p_off0, g_off0);
    cudaGetSymbolAddress((void**)&p_cur0, g_cur0);
    cudaGetSymbolAddress((void**)&p_csr0, g_csr0);
    cudaGetSymbolAddress((void**)&p_cnt1, g_cnt1);
    cudaGetSymbolAddress((void**)&p_off1, g_off1);
    cudaGetSymbolAddress((void**)&p_cur1, g_cur1);
    cudaGetSymbolAddress((void**)&p_csr1, g_csr1);
    cudaGetSymbolAddress((void**)&p_cnt2, g_cnt2);
    cudaGetSymbolAddress((void**)&p_off2, g_off2);
    cudaGetSymbolAddress((void**)&p_cur2, g_cur2);
    cudaGetSymbolAddress((void**)&p_csr2, g_csr2);
    cudaGetSymbolAddress((void**)&p_incl, g_incl);

    zero_cnts<<<512, 256>>>();
    wtrans<<<200, 256>>>(Wl0, Wr0, p_W0, DIN, DH, 2 * DIN);
    wtrans<<<512, 256>>>(Wl1, Wr1, p_W1, DH, DH, 2 * DH);
    wtrans<<<96, 256>>>(Wl2, Wr2, p_W2, DH, DOUTc, 2 * DH);

    // CSR builds (depend only on edge lists)
    hist_k<<<2048, 256>>>(dst0, e0, p_cnt0);
    hist_k<<<1024, 256>>>(dst1, e1, p_cnt1);
    hist_k<<<160, 256>>>(dst2, e2, p_cnt2);

    int nb0 = (N1c + 1023) / 1024;  // 100
    scan_blk<<<nb0, 1024>>>(p_cnt0, N1c, p_incl);
    scan_top<<<1, 256>>>(nb0);
    scan_fin<<<nb0, 1024>>>(p_cnt0, p_incl, N1c, p_off0, p_cur0);
    fill_k<<<2048, 256>>>(src0, dst0, e0, p_cur0, p_csr0);

    int nb1 = (N2c + 1023) / 1024;  // 25
    scan_blk<<<nb1, 1024>>>(p_cnt1, N2c, p_incl);
    scan_top<<<1, 256>>>(nb1);
    scan_fin<<<nb1, 1024>>>(p_cnt1, p_incl, N2c, p_off1, p_cur1);
    fill_k<<<1024, 256>>>(src1, dst1, e1, p_cur1, p_csr1);

    int nb2 = (N3c + 1023) / 1024;  // 4
    scan_blk<<<nb2, 1024>>>(p_cnt2, N3c, p_incl);
    scan_top<<<1, 256>>>(nb2);
    scan_fin<<<nb2, 1024>>>(p_cnt2, p_incl, N3c, p_off2, p_cur2);
    fill_k<<<160, 256>>>(src2, dst2, e2, p_cur2, p_csr2);

    // ---- layer 0 ----
    gather_mean100<<<(N1c * 32 + 255) / 256, 256>>>(x, p_off0, p_csr0, p_mean0, N1c);
    {
        dim3 grid(DH / BN, N1c / BM);
        gemm_dual<<<grid, 256>>>(p_mean0, DIN, x, DIN, p_W0, bl0, p_h1, N1c, DH, 1);
    }

    // ---- layer 1 ----
    gather_mean256<<<(N2c * 32 + 255) / 256, 256>>>(p_h1, p_off1, p_csr1, p_mean1, N2c);
    {
        dim3 grid(DH / BN, N2c / BM);
        gemm_dual<<<grid, 256>>>(p_mean1, DH, p_h1, DH, p_W1, bl1, h2, N2c, DH, 1);
    }

    // ---- layer 2 ----
    gather_mean256<<<(N3c * 32 + 255) / 256, 256>>>(h2, p_off2, p_csr2, p_mean2, N3c);
    layer2_softmax<<<N3c, 64>>>(h2, bl2, h3, lsm);
}

// round 4
// speedup vs baseline: 2.3382x; 1.5755x over previous
#include <cuda_runtime.h>
#include <cuda_bf16.h>
#include <math.h>
#include <stdint.h>

#define N1c 102400
#define N2c 25600
#define N3c 4096
#define E0c 1536000
#define E1c 256000
#define E2c 40960
#define DIN 100
#define DH  256
#define DOUTc 47

// ---------------- scratch (device globals; no allocation allowed) ------------
__device__ float g_mean0[(size_t)N1c * DIN];
__device__ float g_h1[(size_t)N1c * DH];
__device__ float g_mean1[(size_t)N2c * DH];
__device__ float g_mean2[(size_t)N3c * DH];
__device__ float g_W2[(2 * DH) * DOUTc]; // [K=512][N=47]

// CSR scratch
__device__ int g_cnt0[N1c];
__device__ int g_off0[N1c + 1];
__device__ int g_cur0[N1c];
__device__ int g_csr0[E0c];
__device__ int g_cnt1[N2c];
__device__ int g_off1[N2c + 1];
__device__ int g_cur1[N2c];
__device__ int g_csr1[E1c];
__device__ int g_cnt2[N3c];
__device__ int g_off2[N3c + 1];
__device__ int g_cur2[N3c];
__device__ int g_csr2[E2c];
__device__ int g_incl[N1c];
__device__ int g_bsum[256];

// ======================= bf16-split tensor-core GEMM =========================
// C[M,256] = relu?( [A1|A2] @ [B1|B2]^T + bias )
// 3-product split: Ah*Bh + Ah*Bl + Al*Bh with bf16 hi/lo halves.
// Block 128x128, 8 warps (4m x 2n), warp tile 32x64, BK=32 double-buffered.
#define GT 256
// smem: AH[2][128][32]bf16, AL, BH, BL -> 4 * 16384 = 64 KB
#define SM_AH 0
#define SM_AL 16384
#define SM_BH 32768
#define SM_BL 49152
#define SM_BUF 8192
#define SMEM_MMA_TOTAL 65536

__device__ __forceinline__ int sw_addr(int base, int r, int w) {
    // row r (0..127), word w (0..15); XOR swizzle on word-group bits
    return base + r * 64 + (((w ^ (((r >> 1) & 3) << 2))) << 2);
}
__device__ __forceinline__ uint32_t pack_bf16(float a, float b) {
    __nv_bfloat162 h = __floats2bfloat162_rn(a, b);
    return *(uint32_t*)&h;
}
__device__ __forceinline__ void mma_bf16(float* c, const uint32_t* a, const uint32_t* b) {
    asm volatile(
        "mma.sync.aligned.m16n8k16.row.col.f32.bf16.bf16.f32 "
        "{%0,%1,%2,%3}, {%4,%5,%6,%7}, {%8,%9}, {%0,%1,%2,%3};"
        : "+f"(c[0]), "+f"(c[1]), "+f"(c[2]), "+f"(c[3])
        : "r"(a[0]), "r"(a[1]), "r"(a[2]), "r"(a[3]), "r"(b[0]), "r"(b[1]));
}

__global__ void __launch_bounds__(GT, 1)
gemm_mma(const float* __restrict__ A1, int K1f, const float* __restrict__ A2, int K2f,
         const float* __restrict__ B1, const float* __restrict__ B2,
         const float* __restrict__ bias, float* __restrict__ C, int NC, int relu) {
    extern __shared__ char sm[];
    int tid = threadIdx.x;
    int wid = tid >> 5;
    int lane = tid & 31;
    int row0 = blockIdx.x * 128;
    int col0 = blockIdx.y * 128;
    int wm = wid & 3, wn = wid >> 2;

    int r = tid >> 1;        // loader row 0..127
    int o = tid & 1;         // loader k-half (16 floats each)
    int KT = K1f + K2f;      // total in float4 units
    const float4* a1p = (const float4*)(A1 + (size_t)(row0 + r) * (K1f * 4));
    const float4* a2p = (const float4*)(A2 + (size_t)(row0 + r) * (K2f * 4));
    const float4* b1p = (const float4*)(B1 + (size_t)(col0 + r) * (K1f * 4));
    const float4* b2p = (const float4*)(B2 + (size_t)(col0 + r) * (K2f * 4));

    float acc[2][8][4];
    #pragma unroll
    for (int i = 0; i < 2; i++)
        #pragma unroll
        for (int j = 0; j < 8; j++)
            #pragma unroll
            for (int q = 0; q < 4; q++) acc[i][j][q] = 0.f;

    float fa[16], fb[16];

    // ---- helper lambdas (inlined) ----
    auto load_regs = [&](int c) {
        #pragma unroll
        for (int i = 0; i < 4; i++) {
            int F = c * 8 + o * 4 + i;
            float4 va = make_float4(0.f, 0.f, 0.f, 0.f);
            float4 vb = va;
            if (F < K1f) { va = a1p[F]; vb = b1p[F]; }
            else if (F < KT) { va = a2p[F - K1f]; vb = b2p[F - K1f]; }
            fa[4 * i + 0] = va.x; fa[4 * i + 1] = va.y;
            fa[4 * i + 2] = va.z; fa[4 * i + 3] = va.w;
            fb[4 * i + 0] = vb.x; fb[4 * i + 1] = vb.y;
            fb[4 * i + 2] = vb.z; fb[4 * i + 3] = vb.w;
        }
    };
    auto store_smem = [&](int buf) {
        uint32_t ah[8], al[8], bh[8], bl[8];
        #pragma unroll
        for (int j = 0; j < 8; j++) {
            float v0 = fa[2 * j], v1 = fa[2 * j + 1];
            __nv_bfloat16 h0 = __float2bfloat16(v0), h1 = __float2bfloat16(v1);
            ah[j] = pack_bf16(__bfloat162float(h0), __bfloat162float(h1));
            al[j] = pack_bf16(v0 - __bfloat162float(h0), v1 - __bfloat162float(h1));
            float w0 = fb[2 * j], w1 = fb[2 * j + 1];
            __nv_bfloat16 g0 = __float2bfloat16(w0), g1 = __float2bfloat16(w1);
            bh[j] = pack_bf16(__bfloat162float(g0), __bfloat162float(g1));
            bl[j] = pack_bf16(w0 - __bfloat162float(g0), w1 - __bfloat162float(g1));
        }
        int w0i = o * 8;
        *(uint4*)(sm + sw_addr(SM_AH + buf * SM_BUF, r, w0i)) =
            make_uint4(ah[0], ah[1], ah[2], ah[3]);
        *(uint4*)(sm + sw_addr(SM_AH + buf * SM_BUF, r, w0i + 4)) =
            make_uint4(ah[4], ah[5], ah[6], ah[7]);
        *(uint4*)(sm + sw_addr(SM_AL + buf * SM_BUF, r, w0i)) =
            make_uint4(al[0], al[1], al[2], al[3]);
        *(uint4*)(sm + sw_addr(SM_AL + buf * SM_BUF, r, w0i + 4)) =
            make_uint4(al[4], al[5], al[6], al[7]);
        *(uint4*)(sm + sw_addr(SM_BH + buf * SM_BUF, r, w0i)) =
            make_uint4(bh[0], bh[1], bh[2], bh[3]);
        *(uint4*)(sm + sw_addr(SM_BH + buf * SM_BUF, r, w0i + 4)) =
            make_uint4(bh[4], bh[5], bh[6], bh[7]);
        *(uint4*)(sm + sw_addr(SM_BL + buf * SM_BUF, r, w0i)) =
            make_uint4(bl[0], bl[1], bl[2], bl[3]);
        *(uint4*)(sm + sw_addr(SM_BL + buf * SM_BUF, r, w0i + 4)) =
            make_uint4(bl[4], bl[5], bl[6], bl[7]);
    };

    // prologue
    load_regs(0);
    store_smem(0);
    __syncthreads();

    for (int t = 0; t < NC; t++) {
        int buf = t & 1;
        bool has = (t + 1 < NC);
        if (has) load_regs(t + 1);

        #pragma unroll
        for (int s = 0; s < 2; s++) {
            int wbase = s * 8 + (lane & 3);
            uint32_t Ah[2][4], Al[2][4], Bh[8][2], Bl[8][2];
            #pragma unroll
            for (int mi = 0; mi < 2; mi++) {
                int r0 = wm * 32 + mi * 16 + (lane >> 2);
                int r1 = r0 + 8;
                int ahb = SM_AH + buf * SM_BUF;
                int alb = SM_AL + buf * SM_BUF;
                Ah[mi][0] = *(uint32_t*)(sm + sw_addr(ahb, r0, wbase));
                Ah[mi][1] = *(uint32_t*)(sm + sw_addr(ahb, r1, wbase));
                Ah[mi][2] = *(uint32_t*)(sm + sw_addr(ahb, r0, wbase + 4));
                Ah[mi][3] = *(uint32_t*)(sm + sw_addr(ahb, r1, wbase + 4));
                Al[mi][0] = *(uint32_t*)(sm + sw_addr(alb, r0, wbase));
                Al[mi][1] = *(uint32_t*)(sm + sw_addr(alb, r1, wbase));
                Al[mi][2] = *(uint32_t*)(sm + sw_addr(alb, r0, wbase + 4));
                Al[mi][3] = *(uint32_t*)(sm + sw_addr(alb, r1, wbase + 4));
            }
            #pragma unroll
            for (int ni = 0; ni < 8; ni++) {
                int n0 = wn * 64 + ni * 8 + (lane >> 2);
                int bhb = SM_BH + buf * SM_BUF;
                int blb = SM_BL + buf * SM_BUF;
                Bh[ni][0] = *(uint32_t*)(sm + sw_addr(bhb, n0, wbase));
                Bh[ni][1] = *(uint32_t*)(sm + sw_addr(bhb, n0, wbase + 4));
                Bl[ni][0] = *(uint32_t*)(sm + sw_addr(blb, n0, wbase));
                Bl[ni][1] = *(uint32_t*)(sm + sw_addr(blb, n0, wbase + 4));
            }
            #pragma unroll
            for (int mi = 0; mi < 2; mi++)
                #pragma unroll
                for (int ni = 0; ni < 8; ni++) {
                    mma_bf16(acc[mi][ni], Ah[mi], Bh[ni]);
                    mma_bf16(acc[mi][ni], Ah[mi], Bl[ni]);
                    mma_bf16(acc[mi][ni], Al[mi], Bh[ni]);
                }
        }

        if (has) store_smem(buf ^ 1);
        __syncthreads();
    }

    // epilogue
    #pragma unroll
    for (int mi = 0; mi < 2; mi++) {
        int r0 = row0 + wm * 32 + mi * 16 + (lane >> 2);
        #pragma unroll
        for (int ni = 0; ni < 8; ni++) {
            int cb = col0 + wn * 64 + ni * 8 + (lane & 3) * 2;
            float b0 = bias[cb], b1 = bias[cb + 1];
            float v0 = acc[mi][ni][0] + b0;
            float v1 = acc[mi][ni][1] + b1;
            float v2 = acc[mi][ni][2] + b0;
            float v3 = acc[mi][ni][3] + b1;
            if (relu) {
                v0 = fmaxf(v0, 0.f); v1 = fmaxf(v1, 0.f);
                v2 = fmaxf(v2, 0.f); v3 = fmaxf(v3, 0.f);
            }
            *(float2*)(C + (size_t)r0 * 256 + cb) = make_float2(v0, v1);
            *(float2*)(C + (size_t)(r0 + 8) * 256 + cb) = make_float2(v2, v3);
        }
    }
}

// ======================= CSR build ===========================================
__global__ void zero_cnts() {
    int i = blockIdx.x * blockDim.x + threadIdx.x;
    int stride = gridDim.x * blockDim.x;
    for (int t = i; t < N1c; t += stride) g_cnt0[t] = 0;
    for (int t = i; t < N2c; t += stride) g_cnt1[t] = 0;
    for (int t = i; t < N3c; t += stride) g_cnt2[t] = 0;
}

__global__ void hist_k(const int* __restrict__ dst, int E, int* __restrict__ cnt) {
    for (int e = blockIdx.x * blockDim.x + threadIdx.x; e < E;
         e += gridDim.x * blockDim.x)
        atomicAdd(&cnt[dst[e]], 1);
}

__global__ void scan_blk(const int* __restrict__ cnt, int n, int* __restrict__ incl) {
    __shared__ int sh[1024];
    int i = blockIdx.x * 1024 + threadIdx.x;
    int v = (i < n) ? cnt[i] : 0;
    sh[threadIdx.x] = v;
    __syncthreads();
    for (int d = 1; d < 1024; d <<= 1) {
        int t = (threadIdx.x >= d) ? sh[threadIdx.x - d] : 0;
        __syncthreads();
        sh[threadIdx.x] += t;
        __syncthreads();
    }
    if (i < n) incl[i] = sh[threadIdx.x];
    if (threadIdx.x == 1023) g_bsum[blockIdx.x] = sh[1023];
}

__global__ void scan_top(int nb) {
    __shared__ int sh[256];
    int t = threadIdx.x;
    int v = (t < nb) ? g_bsum[t] : 0;
    sh[t] = v;
    __syncthreads();
    for (int d = 1; d < 256; d <<= 1) {
        int u = (t >= d) ? sh[t - d] : 0;
        __syncthreads();
        sh[t] += u;
        __syncthreads();
    }
    if (t < nb) g_bsum[t] = sh[t] - v;
}

__global__ void scan_fin(const int* __restrict__ cnt, const int* __restrict__ incl,
                         int n, int* __restrict__ off, int* __restrict__ cur) {
    int i = blockIdx.x * 1024 + threadIdx.x;
    if (i < n) {
        int o = incl[i] - cnt[i] + g_bsum[blockIdx.x];
        off[i] = o;
        cur[i] = o;
        if (i == n - 1) off[n] = incl[i] + g_bsum[blockIdx.x];
    }
}

__global__ void fill_k(const int* __restrict__ src, const int* __restrict__ dst, int E,
                       int* __restrict__ cur, int* __restrict__ csr) {
    for (int e = blockIdx.x * blockDim.x + threadIdx.x; e < E;
         e += gridDim.x * blockDim.x) {
        int p = atomicAdd(&cur[dst[e]], 1);
        csr[p] = src[e];
    }
}

// ======================= gather means ========================================
__global__ void gather_mean100(const float* __restrict__ x, const int* __restrict__ off,
                               const int* __restrict__ csr, float* __restrict__ mean,
                               int n) {
    int w = (blockIdx.x * blockDim.x + threadIdx.x) >> 5;
    int lane = threadIdx.x & 31;
    if (w >= n) return;
    int e0 = off[w], e1 = off[w + 1];
    float4 acc = make_float4(0.f, 0.f, 0.f, 0.f);
    for (int e = e0; e < e1; e++) {
        int s = csr[e];
        if (lane < 25) {
            float4 v = *((const float4*)(x + (size_t)s * DIN) + lane);
            acc.x += v.x; acc.y += v.y; acc.z += v.z; acc.w += v.w;
        }
    }
    float inv = 1.f / fmaxf((float)(e1 - e0), 1.f);
    if (lane < 25) {
        acc.x *= inv; acc.y *= inv; acc.z *= inv; acc.w *= inv;
        *((float4*)(mean + (size_t)w * DIN) + lane) = acc;
    }
}

__global__ void gather_mean256(const float* __restrict__ xin, const int* __restrict__ off,
                               const int* __restrict__ csr, float* __restrict__ mean,
                               int n) {
    int w = (blockIdx.x * blockDim.x + threadIdx.x) >> 5;
    int lane = threadIdx.x & 31;
    if (w >= n) return;
    int e0 = off[w], e1 = off[w + 1];
    float4 a0 = make_float4(0.f, 0.f, 0.f, 0.f);
    float4 a1 = a0;
    for (int e = e0; e < e1; e++) {
        int s = csr[e];
        const float4* xs = (const float4*)(xin + (size_t)s * DH);
        float4 v0 = xs[lane];
        float4 v1 = xs[lane + 32];
        a0.x += v0.x; a0.y += v0.y; a0.z += v0.z; a0.w += v0.w;
        a1.x += v1.x; a1.y += v1.y; a1.z += v1.z; a1.w += v1.w;
    }
    float inv = 1.f / fmaxf((float)(e1 - e0), 1.f);
    a0.x *= inv; a0.y *= inv; a0.z *= inv; a0.w *= inv;
    a1.x *= inv; a1.y *= inv; a1.z *= inv; a1.w *= inv;
    float4* mp = (float4*)(mean + (size_t)w * DH);
    mp[lane] = a0;
    mp[lane + 32] = a1;
}

// ======================= layer-2 weight concat + fused layer2 ================
__global__ void wtrans(const float* __restrict__ Wl, const float* __restrict__ Wr,
                       float* __restrict__ Wc, int d, int n, int K) {
    int total = K * n;
    for (int idx = blockIdx.x * blockDim.x + threadIdx.x; idx < total;
         idx += gridDim.x * blockDim.x) {
        int k = idx / n;
        int col = idx % n;
        float v = (k < d) ? Wl[col * d + k] : Wr[col * d + (k - d)];
        Wc[idx] = v;
    }
}

__global__ void layer2_softmax(const float* __restrict__ h2, const float* __restrict__ bias,
                               float* __restrict__ h3out, float* __restrict__ lsmout) {
    int r = blockIdx.x;
    __shared__ float a[2 * DH];
    __shared__ float vals[DOUTc];
    __shared__ float Lse;
    for (int k = threadIdx.x; k < DH; k += blockDim.x)
        a[k] = g_mean2[(size_t)r * DH + k];
    for (int k = threadIdx.x; k < DH; k += blockDim.x)
        a[DH + k] = h2[(size_t)r * DH + k];
    __syncthreads();
    int j = threadIdx.x;
    float v = 0.f;
    if (j < DOUTc) {
        v = bias[j];
        #pragma unroll 8
        for (int k = 0; k < 2 * DH; k++) v += a[k] * g_W2[k * DOUTc + j];
        vals[j] = v;
        h3out[(size_t)r * DOUTc + j] = v;
    }
    __syncthreads();
    if (threadIdx.x == 0) {
        float mmax = -1e30f;
        for (int t = 0; t < DOUTc; t++) mmax = fmaxf(mmax, vals[t]);
        float s = 0.f;
        for (int t = 0; t < DOUTc; t++) s += expf(vals[t] - mmax);
        Lse = mmax + logf(s);
    }
    __syncthreads();
    if (j < DOUTc) lsmout[(size_t)r * DOUTc + j] = v - Lse;
}

// ======================= launch ==============================================
extern "C" void kernel_launch(void* const* d_in, const int* in_sizes, int n_in,
                              void* d_out, int out_size) {
    const float* x   = (const float*)d_in[0];
    const float* Wl0 = (const float*)d_in[1];
    const float* bl0 = (const float*)d_in[2];
    const float* Wr0 = (const float*)d_in[3];
    const float* Wl1 = (const float*)d_in[4];
    const float* bl1 = (const float*)d_in[5];
    const float* Wr1 = (const float*)d_in[6];
    const float* Wl2 = (const float*)d_in[7];
    const float* bl2 = (const float*)d_in[8];
    const float* Wr2 = (const float*)d_in[9];
    const int* src0 = (const int*)d_in[10];
    const int* dst0 = (const int*)d_in[11];
    const int* src1 = (const int*)d_in[12];
    const int* dst1 = (const int*)d_in[13];
    const int* src2 = (const int*)d_in[14];
    const int* dst2 = (const int*)d_in[15];

    int e0 = in_sizes[10], e1 = in_sizes[12], e2 = in_sizes[14];

    float* out = (float*)d_out;
    float* lsm = out;                       // 4096*47
    float* h3  = out + (size_t)N3c * DOUTc; // 4096*47
    float* h2  = h3 + (size_t)N3c * DOUTc;  // 25600*256

    float *p_mean0, *p_h1, *p_mean1, *p_mean2, *p_W2;
    cudaGetSymbolAddress((void**)&p_mean0, g_mean0);
    cudaGetSymbolAddress((void**)&p_h1,    g_h1);
    cudaGetSymbolAddress((void**)&p_mean1, g_mean1);
    cudaGetSymbolAddress((void**)&p_mean2, g_mean2);
    cudaGetSymbolAddress((void**)&p_W2,    g_W2);
    int *p_cnt0, *p_off0, *p_cur0, *p_csr0;
    int *p_cnt1, *p_off1, *p_cur1, *p_csr1;
    int *p_cnt2, *p_off2, *p_cur2, *p_csr2;
    int *p_incl;
    cudaGetSymbolAddress((void**)&p_cnt0, g_cnt0);
    cudaGetSymbolAddress((void**)&p_off0, g_off0);
    cudaGetSymbolAddress((void**)&p_cur0, g_cur0);
    cudaGetSymbolAddress((void**)&p_csr0, g_csr0);
    cudaGetSymbolAddress((void**)&p_cnt1, g_cnt1);
    cudaGetSymbolAddress((void**)&p_off1, g_off1);
    cudaGetSymbolAddress((void**)&p_cur1, g_cur1);
    cudaGetSymbolAddress((void**)&p_csr1, g_csr1);
    cudaGetSymbolAddress((void**)&p_cnt2, g_cnt2);
    cudaGetSymbolAddress((void**)&p_off2, g_off2);
    cudaGetSymbolAddress((void**)&p_cur2, g_cur2);
    cudaGetSymbolAddress((void**)&p_csr2, g_csr2);
    cudaGetSymbolAddress((void**)&p_incl, g_incl);

    cudaFuncSetAttribute(gemm_mma, cudaFuncAttributeMaxDynamicSharedMemorySize,
                         SMEM_MMA_TOTAL);

    zero_cnts<<<512, 256>>>();
    hist_k<<<2048, 256>>>(dst0, e0, p_cnt0);
    int nb0 = (N1c + 1023) / 1024;  // 100
    scan_blk<<<nb0, 1024>>>(p_cnt0, N1c, p_incl);
    scan_top<<<1, 256>>>(nb0);
    scan_fin<<<nb0, 1024>>>(p_cnt0, p_incl, N1c, p_off0, p_cur0);
    fill_k<<<2048, 256>>>(src0, dst0, e0, p_cur0, p_csr0);

    // ---- layer 0 ----  (K1=100 -> 25 f4, K2=100 -> 25 f4, NC=ceil(200/32)=7)
    gather_mean100<<<(N1c * 32 + 255) / 256, 256>>>(x, p_off0, p_csr0, p_mean0, N1c);
    {
        dim3 grid(N1c / 128, 2);
        gemm_mma<<<grid, GT, SMEM_MMA_TOTAL>>>(p_mean0, 25, x, 25, Wl0, Wr0,
                                               bl0, p_h1, 7, 1);
    }

    // CSR layer 1
    hist_k<<<1024, 256>>>(dst1, e1, p_cnt1);
    int nb1 = (N2c + 1023) / 1024;  // 25
    scan_blk<<<nb1, 1024>>>(p_cnt1, N2c, p_incl);
    scan_top<<<1, 256>>>(nb1);
    scan_fin<<<nb1, 1024>>>(p_cnt1, p_incl, N2c, p_off1, p_cur1);
    fill_k<<<1024, 256>>>(src1, dst1, e1, p_cur1, p_csr1);

    // ---- layer 1 ----  (K1=K2=256 -> 64 f4 each, NC=512/32=16)
    gather_mean256<<<(N2c * 32 + 255) / 256, 256>>>(p_h1, p_off1, p_csr1, p_mean1, N2c);
    {
        dim3 grid(N2c / 128, 2);
        gemm_mma<<<grid, GT, SMEM_MMA_TOTAL>>>(p_mean1, 64, p_h1, 64, Wl1, Wr1,
                                               bl1, h2, 16, 1);
    }

    // CSR layer 2
    hist_k<<<160, 256>>>(dst2, e2, p_cnt2);
    int nb2 = (N3c + 1023) / 1024;  // 4
    scan_blk<<<nb2, 1024>>>(p_cnt2, N3c, p_incl);
    scan_top<<<1, 256>>>(nb2);
    scan_fin<<<nb2, 1024>>>(p_cnt2, p_incl, N3c, p_off2, p_cur2);
    fill_k<<<160, 256>>>(src2, dst2, e2, p_cur2, p_csr2);
    wtrans<<<96, 256>>>(Wl2, Wr2, p_W2, DH, DOUTc, 2 * DH);

    // ---- layer 2 ----
    gather_mean256<<<(N3c * 32 + 255) / 256, 256>>>(h2, p_off2, p_csr2, p_mean2, N3c);
    layer2_softmax<<<N3c, 64>>>(h2, bl2, h3, lsm);
}